// round 16
// baseline (speedup 1.0000x reference)
#include <cuda_runtime.h>
#include <math.h>

#define NN 2048
#define DHH 256
#define DKK 64
#define FF 32

typedef unsigned long long u64;

// ---------- packed f32x2 helpers (Blackwell FFMA2 path) ----------
__device__ __forceinline__ u64 pack2(float x, float y) {
    u64 r; asm("mov.b64 %0, {%1,%2};" : "=l"(r) : "f"(x), "f"(y)); return r;
}
__device__ __forceinline__ u64 splat2(float x) { return pack2(x, x); }
__device__ __forceinline__ float2 unpack2(u64 v) {
    float2 r; asm("mov.b64 {%0,%1}, %2;" : "=f"(r.x), "=f"(r.y) : "l"(v)); return r;
}
__device__ __forceinline__ u64 ffma2(u64 a, u64 b, u64 c) {
    u64 d; asm("fma.rn.f32x2 %0, %1, %2, %3;" : "=l"(d) : "l"(a), "l"(b), "l"(c)); return d;
}
__device__ __forceinline__ u64 relu2(u64 v) {
    float2 f = unpack2(v);
    f.x = fmaxf(f.x, 0.0f);
    f.y = fmaxf(f.y, 0.0f);
    return pack2(f.x, f.y);
}

// ---------- scratch (static device allocations; no dynamic alloc) ----------
__device__ float g_q[NN * DKK];
__device__ float g_k[NN * DKK];
__device__ float g_v[NN * DHH];
__device__ float g_L[(size_t)NN * NN];   // scores -> logits -> exp(logits - max), all in place
__device__ float g_rs[NN];               // 1 / rowsum

// ============================================================
// K1: C (NN x P) = X (NN x 256) @ W (256 x P) + bias
// tiles 64x64, K-chunk 32, 4x4 micro, 256 threads
// ============================================================
__global__ __launch_bounds__(256) void k_gemm_xw(
    const float* __restrict__ X, const float* __restrict__ W,
    const float* __restrict__ bias, float* __restrict__ C, int P)
{
    __shared__ __align__(16) float As[32][68];  // As[kk][row] (transposed X tile)
    __shared__ __align__(16) float Bs[32][64];  // Bs[kk][col]

    const int tid = threadIdx.x;
    const int tx = tid & 15;
    const int ty = tid >> 4;
    const int r0 = blockIdx.y * 64;
    const int c0 = blockIdx.x * 64;

    float acc[4][4] = {};

    for (int k0 = 0; k0 < 256; k0 += 32) {
        __syncthreads();
        // X tile: 64 rows x 32 k, transpose into As
        #pragma unroll
        for (int it = 0; it < 2; it++) {
            int idx = tid + it * 256;       // 0..511
            int rr = idx >> 3;              // 0..63
            int cc = idx & 7;               // 0..7 float4 groups
            float4 xv = *(const float4*)(X + (size_t)(r0 + rr) * 256 + k0 + cc * 4);
            As[cc * 4 + 0][rr] = xv.x;
            As[cc * 4 + 1][rr] = xv.y;
            As[cc * 4 + 2][rr] = xv.z;
            As[cc * 4 + 3][rr] = xv.w;
        }
        // W tile: 32 k x 64 cols
        #pragma unroll
        for (int it = 0; it < 2; it++) {
            int idx = tid + it * 256;
            int rr = idx >> 4;              // 0..31
            int cc = idx & 15;              // 0..15
            *(float4*)(&Bs[rr][cc * 4]) =
                *(const float4*)(W + (size_t)(k0 + rr) * P + c0 + cc * 4);
        }
        __syncthreads();
        #pragma unroll
        for (int kk = 0; kk < 32; kk++) {
            float a[4], b[4];
            *(float4*)a = *(const float4*)(&As[kk][ty * 4]);
            *(float4*)b = *(const float4*)(&Bs[kk][tx * 4]);
            #pragma unroll
            for (int i2 = 0; i2 < 4; i2++)
                #pragma unroll
                for (int j2 = 0; j2 < 4; j2++)
                    acc[i2][j2] = fmaf(a[i2], b[j2], acc[i2][j2]);
        }
    }

    #pragma unroll
    for (int i2 = 0; i2 < 4; i2++) {
        int c = c0 + tx * 4;
        float4 o;
        o.x = acc[i2][0] + bias[c + 0];
        o.y = acc[i2][1] + bias[c + 1];
        o.z = acc[i2][2] + bias[c + 2];
        o.w = acc[i2][3] + bias[c + 3];
        *(float4*)(C + (size_t)(r0 + ty * 4 + i2) * P + c) = o;
    }
}

// ============================================================
// K2: scores[i][j] = sum_d k[i][d] * q[j][d]   (K = 64, one shot)
// tiles 64x64, f32x2 micro
// ============================================================
__global__ __launch_bounds__(256) void k_scores()
{
    __shared__ __align__(16) float Ks[64][68];  // Ks[d][i_local]
    __shared__ __align__(16) float Qs[64][68];  // Qs[d][j_local]

    const int tid = threadIdx.x;
    const int tx = tid & 15;
    const int ty = tid >> 4;
    const int i0 = blockIdx.y * 64;
    const int j0 = blockIdx.x * 64;

    #pragma unroll
    for (int it = 0; it < 4; it++) {
        int idx = tid + it * 256;   // 0..1023
        int rr = idx >> 4;          // 0..63 rows
        int cc = idx & 15;          // 0..15 d-groups
        float4 kv = *(const float4*)(g_k + (size_t)(i0 + rr) * DKK + cc * 4);
        Ks[cc * 4 + 0][rr] = kv.x; Ks[cc * 4 + 1][rr] = kv.y;
        Ks[cc * 4 + 2][rr] = kv.z; Ks[cc * 4 + 3][rr] = kv.w;
        float4 qv = *(const float4*)(g_q + (size_t)(j0 + rr) * DKK + cc * 4);
        Qs[cc * 4 + 0][rr] = qv.x; Qs[cc * 4 + 1][rr] = qv.y;
        Qs[cc * 4 + 2][rr] = qv.z; Qs[cc * 4 + 3][rr] = qv.w;
    }
    __syncthreads();

    u64 acc[4][2] = {};
    #pragma unroll
    for (int d = 0; d < 64; d++) {
        float a[4];
        *(float4*)a = *(const float4*)(&Ks[d][ty * 4]);
        u64 b0 = *(const u64*)(&Qs[d][tx * 4]);
        u64 b1 = *(const u64*)(&Qs[d][tx * 4 + 2]);
        #pragma unroll
        for (int q = 0; q < 4; q++) {
            u64 aq = splat2(a[q]);
            acc[q][0] = ffma2(aq, b0, acc[q][0]);
            acc[q][1] = ffma2(aq, b1, acc[q][1]);
        }
    }

    #pragma unroll
    for (int q = 0; q < 4; q++) {
        float2 o0 = unpack2(acc[q][0]);
        float2 o1 = unpack2(acc[q][1]);
        float4 o = make_float4(o0.x, o0.y, o1.x, o1.y);
        *(float4*)(g_L + (size_t)(i0 + ty * 4 + q) * NN + j0 + tx * 4) = o;
    }
}

// ============================================================
// K3: per-edge MLP, 2 edges per thread packed f32x2.
// reads scores/adj/dense, writes logits in place over g_L.
// FMA-pipe bound: 1152 FFMA2 per thread; weight operands are
// pre-splatted (w,w) in SMEM -> 1 broadcast LDS.64 per FFMA2
// (dual-issued in the rt=2 gaps of the FMA pipe).
// ============================================================
__global__ __launch_bounds__(128) void k_mlp(
    const float* __restrict__ adj, const float* __restrict__ dense,
    const float* __restrict__ W1, const float* __restrict__ b1,
    const float* __restrict__ W2, const float* __restrict__ b2,
    const float* __restrict__ W3, const float* __restrict__ b3)
{
    __shared__ u64 sW1s[FF], sW1a[FF], sW1d[FF], sB1[FF];
    __shared__ u64 sW2[FF * FF];
    __shared__ u64 sB2[FF], sW3[FF];
    __shared__ float sB3;

    const int tid = threadIdx.x;
    if (tid < FF) {
        sW1s[tid] = splat2(W1[tid]);            // feats[...,0] = scores
        sW1a[tid] = splat2(W1[FF + tid]);       // feats[...,1] = adj
        sW1d[tid] = splat2(W1[2 * FF + tid]);   // feats[...,2] = dense
        sB1[tid]  = splat2(b1[tid]);
        sB2[tid]  = splat2(b2[tid]);
        sW3[tid]  = splat2(W3[tid]);
    }
    for (int t = tid; t < FF * FF; t += 128) sW2[t] = splat2(W2[t]);
    if (tid == 0) sB3 = b3[0];
    __syncthreads();

    const int i  = blockIdx.y;
    const int jp = blockIdx.x * 128 + tid;      // pair index, j0 = 2*jp
    const size_t off = (size_t)i * NN + (size_t)jp * 2;

    float2 s2 = *(const float2*)(g_L + off);
    float2 a2 = *(const float2*)(adj + off);
    float2 d2 = *(const float2*)(dense + off);
    u64 s = pack2(s2.x, s2.y);
    u64 a = pack2(a2.x, a2.y);
    u64 d = pack2(d2.x, d2.y);

    // layer 1: 3 -> 32
    u64 h1[FF];
    #pragma unroll
    for (int u = 0; u < FF; u++) {
        u64 t = ffma2(d, sW1d[u], sB1[u]);
        t = ffma2(a, sW1a[u], t);
        t = ffma2(s, sW1s[u], t);
        h1[u] = relu2(t);
    }

    // layer 2: 32 -> 32  (1024 FFMA2)
    u64 acc[FF];
    #pragma unroll
    for (int u = 0; u < FF; u++) acc[u] = sB2[u];
    #pragma unroll
    for (int p = 0; p < FF; p++) {
        u64 h = h1[p];
        #pragma unroll
        for (int u = 0; u < FF; u++)
            acc[u] = ffma2(h, sW2[p * FF + u], acc[u]);
    }

    // layer 3: 32 -> 1
    u64 lg = splat2(sB3);
    #pragma unroll
    for (int u = 0; u < FF; u++)
        lg = ffma2(relu2(acc[u]), sW3[u], lg);

    *(float2*)(g_L + off) = unpack2(lg);
}

// ============================================================
// K4: per-row softmax prep: in-place e = exp(logit - rowmax),
// g_rs[i] = 1 / rowsum. One block per row, 256 threads x 8 elems.
// ============================================================
__global__ __launch_bounds__(256) void k_softmax()
{
    __shared__ float red[8];
    const int i = blockIdx.x;
    const int tid = threadIdx.x;
    float4* row = (float4*)(g_L + (size_t)i * NN);

    float4 v0 = row[tid];
    float4 v1 = row[tid + 256];

    float m = fmaxf(fmaxf(fmaxf(v0.x, v0.y), fmaxf(v0.z, v0.w)),
                    fmaxf(fmaxf(v1.x, v1.y), fmaxf(v1.z, v1.w)));
    #pragma unroll
    for (int o = 16; o; o >>= 1) m = fmaxf(m, __shfl_xor_sync(0xffffffffu, m, o));
    if ((tid & 31) == 0) red[tid >> 5] = m;
    __syncthreads();
    float mm = red[0];
    #pragma unroll
    for (int w = 1; w < 8; w++) mm = fmaxf(mm, red[w]);

    v0.x = __expf(v0.x - mm); v0.y = __expf(v0.y - mm);
    v0.z = __expf(v0.z - mm); v0.w = __expf(v0.w - mm);
    v1.x = __expf(v1.x - mm); v1.y = __expf(v1.y - mm);
    v1.z = __expf(v1.z - mm); v1.w = __expf(v1.w - mm);
    row[tid] = v0;
    row[tid + 256] = v1;

    float sum = ((v0.x + v0.y) + (v0.z + v0.w)) + ((v1.x + v1.y) + (v1.z + v1.w));
    #pragma unroll
    for (int o = 16; o; o >>= 1) sum += __shfl_xor_sync(0xffffffffu, sum, o);
    __syncthreads();                 // protect red reuse
    if ((tid & 31) == 0) red[tid >> 5] = sum;
    __syncthreads();
    if (tid == 0) {
        float tot = 0.0f;
        #pragma unroll
        for (int w = 0; w < 8; w++) tot += red[w];
        g_rs[i] = 1.0f / tot;
    }
}

// ============================================================
// K5: out[i][c] = (1/rowsum_i) * sum_j E[i][j] * v[j][c]
// tiles 64(M) x 64(N), K-chunk 32, f32x2 micro (4 rows x 2 col-pairs)
// ============================================================
__global__ __launch_bounds__(256) void k_av(float* __restrict__ out)
{
    __shared__ __align__(16) float Es[32][68];  // Es[kk][row] (transposed E tile)
    __shared__ __align__(16) float Vs[32][64];  // Vs[kk][col]

    const int tid = threadIdx.x;
    const int tx = tid & 15;
    const int ty = tid >> 4;
    const int r0 = blockIdx.y * 64;
    const int c0 = blockIdx.x * 64;

    u64 acc[4][2] = {};

    for (int k0 = 0; k0 < NN; k0 += 32) {
        __syncthreads();
        // E tile: 64 rows x 32 j, transpose into Es
        #pragma unroll
        for (int it = 0; it < 2; it++) {
            int idx = tid + it * 256;
            int rr = idx >> 3;          // 0..63
            int cc = idx & 7;
            float4 ev = *(const float4*)(g_L + (size_t)(r0 + rr) * NN + k0 + cc * 4);
            Es[cc * 4 + 0][rr] = ev.x;
            Es[cc * 4 + 1][rr] = ev.y;
            Es[cc * 4 + 2][rr] = ev.z;
            Es[cc * 4 + 3][rr] = ev.w;
        }
        // V tile: 32 j x 64 cols
        #pragma unroll
        for (int it = 0; it < 2; it++) {
            int idx = tid + it * 256;
            int rr = idx >> 4;          // 0..31
            int cc = idx & 15;
            *(float4*)(&Vs[rr][cc * 4]) =
                *(const float4*)(g_v + (size_t)(k0 + rr) * DHH + c0 + cc * 4);
        }
        __syncthreads();
        #pragma unroll
        for (int kk = 0; kk < 32; kk++) {
            float a[4];
            *(float4*)a = *(const float4*)(&Es[kk][ty * 4]);
            u64 b0 = *(const u64*)(&Vs[kk][tx * 4]);
            u64 b1 = *(const u64*)(&Vs[kk][tx * 4 + 2]);
            #pragma unroll
            for (int q = 0; q < 4; q++) {
                u64 aq = splat2(a[q]);
                acc[q][0] = ffma2(aq, b0, acc[q][0]);
                acc[q][1] = ffma2(aq, b1, acc[q][1]);
            }
        }
    }

    #pragma unroll
    for (int q = 0; q < 4; q++) {
        int r = r0 + ty * 4 + q;
        float rs = g_rs[r];
        float2 o0 = unpack2(acc[q][0]);
        float2 o1 = unpack2(acc[q][1]);
        float4 o = make_float4(o0.x * rs, o0.y * rs, o1.x * rs, o1.y * rs);
        *(float4*)(out + (size_t)r * DHH + c0 + tx * 4) = o;
    }
}

// ============================================================
extern "C" void kernel_launch(void* const* d_in, const int* in_sizes, int n_in,
                              void* d_out, int out_size)
{
    (void)in_sizes; (void)n_in; (void)out_size;
    const float* x     = (const float*)d_in[0];
    const float* adj   = (const float*)d_in[1];
    const float* dense = (const float*)d_in[2];
    const float* Wq    = (const float*)d_in[3];
    const float* bq    = (const float*)d_in[4];
    const float* Wk    = (const float*)d_in[5];
    const float* bk    = (const float*)d_in[6];
    const float* Wv    = (const float*)d_in[7];
    const float* bv    = (const float*)d_in[8];
    const float* W1    = (const float*)d_in[9];
    const float* b1    = (const float*)d_in[10];
    const float* W2    = (const float*)d_in[11];
    const float* b2    = (const float*)d_in[12];
    const float* W3    = (const float*)d_in[13];
    const float* b3    = (const float*)d_in[14];
    float* out = (float*)d_out;

    float *qp, *kp, *vp;
    cudaGetSymbolAddress((void**)&qp, g_q);
    cudaGetSymbolAddress((void**)&kp, g_k);
    cudaGetSymbolAddress((void**)&vp, g_v);

    // K1: projections
    k_gemm_xw<<<dim3(1, NN / 64), 256>>>(x, Wq, bq, qp, DKK);
    k_gemm_xw<<<dim3(1, NN / 64), 256>>>(x, Wk, bk, kp, DKK);
    k_gemm_xw<<<dim3(DHH / 64, NN / 64), 256>>>(x, Wv, bv, vp, DHH);
    // K2: scores = k @ q^T -> g_L
    k_scores<<<dim3(NN / 64, NN / 64), 256>>>();
    // K3: per-edge MLP -> logits in place
    k_mlp<<<dim3(NN / 256, NN), 128>>>(adj, dense, W1, b1, W2, b2, W3, b3);
    // K4: exp(logit - rowmax) in place + 1/rowsum
    k_softmax<<<NN, 256>>>();
    // K5: feature = focus @ v
    k_av<<<dim3(DHH / 64, NN / 64), 256>>>(out);
}

// round 17
// speedup vs baseline: 1.0267x; 1.0267x over previous
#include <cuda_runtime.h>
#include <math.h>

#define NN 2048
#define DHH 256
#define DKK 64
#define FF 32

typedef unsigned long long u64;

// ---------- packed f32x2 helpers (Blackwell FFMA2 path) ----------
__device__ __forceinline__ u64 pack2(float x, float y) {
    u64 r; asm("mov.b64 %0, {%1,%2};" : "=l"(r) : "f"(x), "f"(y)); return r;
}
__device__ __forceinline__ u64 splat2(float x) { return pack2(x, x); }
__device__ __forceinline__ float2 unpack2(u64 v) {
    float2 r; asm("mov.b64 {%0,%1}, %2;" : "=f"(r.x), "=f"(r.y) : "l"(v)); return r;
}
__device__ __forceinline__ u64 ffma2(u64 a, u64 b, u64 c) {
    u64 d; asm("fma.rn.f32x2 %0, %1, %2, %3;" : "=l"(d) : "l"(a), "l"(b), "l"(c)); return d;
}
__device__ __forceinline__ u64 relu2(u64 v) {
    float2 f = unpack2(v);
    f.x = fmaxf(f.x, 0.0f);
    f.y = fmaxf(f.y, 0.0f);
    return pack2(f.x, f.y);
}

// ---------- scratch (static device allocations; no dynamic alloc) ----------
__device__ float g_q[NN * DKK];
__device__ float g_k[NN * DKK];
__device__ float g_v[NN * DHH];
__device__ float g_L[(size_t)NN * NN];   // scores -> logits -> exp(logits - max), in place
__device__ float g_rs[NN];               // 1 / rowsum

// ============================================================
// K1a: fused q/k projection. blockIdx.z: 0 -> q (Wq,bq), 1 -> k (Wk,bk).
// C (NN x 64) = X (NN x 256) @ W (256 x 64) + bias
// ============================================================
__global__ __launch_bounds__(256) void k_gemm_qk(
    const float* __restrict__ X,
    const float* __restrict__ Wq, const float* __restrict__ bq,
    const float* __restrict__ Wk, const float* __restrict__ bk,
    float* __restrict__ Cq, float* __restrict__ Ck)
{
    const float* W    = blockIdx.z ? Wk : Wq;
    const float* bias = blockIdx.z ? bk : bq;
    float*       C    = blockIdx.z ? Ck : Cq;

    __shared__ __align__(16) float As[32][68];
    __shared__ __align__(16) float Bs[32][64];

    const int tid = threadIdx.x;
    const int tx = tid & 15;
    const int ty = tid >> 4;
    const int r0 = blockIdx.y * 64;

    float acc[4][4] = {};

    for (int k0 = 0; k0 < 256; k0 += 32) {
        __syncthreads();
        #pragma unroll
        for (int it = 0; it < 2; it++) {
            int idx = tid + it * 256;
            int rr = idx >> 3;
            int cc = idx & 7;
            float4 xv = *(const float4*)(X + (size_t)(r0 + rr) * 256 + k0 + cc * 4);
            As[cc * 4 + 0][rr] = xv.x; As[cc * 4 + 1][rr] = xv.y;
            As[cc * 4 + 2][rr] = xv.z; As[cc * 4 + 3][rr] = xv.w;
        }
        {
            int rr = tid >> 4;          // 0..15 -> need 32 rows: two passes
            int cc = tid & 15;
            *(float4*)(&Bs[rr][cc * 4]) =
                *(const float4*)(W + (size_t)(k0 + rr) * 64 + cc * 4);
            *(float4*)(&Bs[rr + 16][cc * 4]) =
                *(const float4*)(W + (size_t)(k0 + rr + 16) * 64 + cc * 4);
        }
        __syncthreads();
        #pragma unroll
        for (int kk = 0; kk < 32; kk++) {
            float a[4], b[4];
            *(float4*)a = *(const float4*)(&As[kk][ty * 4]);
            *(float4*)b = *(const float4*)(&Bs[kk][tx * 4]);
            #pragma unroll
            for (int i2 = 0; i2 < 4; i2++)
                #pragma unroll
                for (int j2 = 0; j2 < 4; j2++)
                    acc[i2][j2] = fmaf(a[i2], b[j2], acc[i2][j2]);
        }
    }

    #pragma unroll
    for (int i2 = 0; i2 < 4; i2++) {
        int c = tx * 4;
        float4 o;
        o.x = acc[i2][0] + bias[c + 0];
        o.y = acc[i2][1] + bias[c + 1];
        o.z = acc[i2][2] + bias[c + 2];
        o.w = acc[i2][3] + bias[c + 3];
        *(float4*)(C + (size_t)(r0 + ty * 4 + i2) * 64 + c) = o;
    }
}

// ============================================================
// K1b: v projection. C (NN x 256) = X @ Wv + bv
// ============================================================
__global__ __launch_bounds__(256) void k_gemm_v(
    const float* __restrict__ X, const float* __restrict__ W,
    const float* __restrict__ bias, float* __restrict__ C)
{
    __shared__ __align__(16) float As[32][68];
    __shared__ __align__(16) float Bs[32][64];

    const int tid = threadIdx.x;
    const int tx = tid & 15;
    const int ty = tid >> 4;
    const int r0 = blockIdx.y * 64;
    const int c0 = blockIdx.x * 64;

    float acc[4][4] = {};

    for (int k0 = 0; k0 < 256; k0 += 32) {
        __syncthreads();
        #pragma unroll
        for (int it = 0; it < 2; it++) {
            int idx = tid + it * 256;
            int rr = idx >> 3;
            int cc = idx & 7;
            float4 xv = *(const float4*)(X + (size_t)(r0 + rr) * 256 + k0 + cc * 4);
            As[cc * 4 + 0][rr] = xv.x; As[cc * 4 + 1][rr] = xv.y;
            As[cc * 4 + 2][rr] = xv.z; As[cc * 4 + 3][rr] = xv.w;
        }
        #pragma unroll
        for (int it = 0; it < 2; it++) {
            int idx = tid + it * 256;
            int rr = idx >> 4;
            int cc = idx & 15;
            *(float4*)(&Bs[rr][cc * 4]) =
                *(const float4*)(W + (size_t)(k0 + rr) * DHH + c0 + cc * 4);
        }
        __syncthreads();
        #pragma unroll
        for (int kk = 0; kk < 32; kk++) {
            float a[4], b[4];
            *(float4*)a = *(const float4*)(&As[kk][ty * 4]);
            *(float4*)b = *(const float4*)(&Bs[kk][tx * 4]);
            #pragma unroll
            for (int i2 = 0; i2 < 4; i2++)
                #pragma unroll
                for (int j2 = 0; j2 < 4; j2++)
                    acc[i2][j2] = fmaf(a[i2], b[j2], acc[i2][j2]);
        }
    }

    #pragma unroll
    for (int i2 = 0; i2 < 4; i2++) {
        int c = c0 + tx * 4;
        float4 o;
        o.x = acc[i2][0] + bias[c + 0];
        o.y = acc[i2][1] + bias[c + 1];
        o.z = acc[i2][2] + bias[c + 2];
        o.w = acc[i2][3] + bias[c + 3];
        *(float4*)(C + (size_t)(r0 + ty * 4 + i2) * DHH + c) = o;
    }
}

// ============================================================
// K2: scores[i][j] = sum_d k[i][d] * q[j][d]   (K = 64, one shot)
// ============================================================
__global__ __launch_bounds__(256) void k_scores()
{
    __shared__ __align__(16) float Ks[64][68];
    __shared__ __align__(16) float Qs[64][68];

    const int tid = threadIdx.x;
    const int tx = tid & 15;
    const int ty = tid >> 4;
    const int i0 = blockIdx.y * 64;
    const int j0 = blockIdx.x * 64;

    #pragma unroll
    for (int it = 0; it < 4; it++) {
        int idx = tid + it * 256;
        int rr = idx >> 4;
        int cc = idx & 15;
        float4 kv = *(const float4*)(g_k + (size_t)(i0 + rr) * DKK + cc * 4);
        Ks[cc * 4 + 0][rr] = kv.x; Ks[cc * 4 + 1][rr] = kv.y;
        Ks[cc * 4 + 2][rr] = kv.z; Ks[cc * 4 + 3][rr] = kv.w;
        float4 qv = *(const float4*)(g_q + (size_t)(j0 + rr) * DKK + cc * 4);
        Qs[cc * 4 + 0][rr] = qv.x; Qs[cc * 4 + 1][rr] = qv.y;
        Qs[cc * 4 + 2][rr] = qv.z; Qs[cc * 4 + 3][rr] = qv.w;
    }
    __syncthreads();

    u64 acc[4][2] = {};
    #pragma unroll
    for (int d = 0; d < 64; d++) {
        float a[4];
        *(float4*)a = *(const float4*)(&Ks[d][ty * 4]);
        u64 b0 = *(const u64*)(&Qs[d][tx * 4]);
        u64 b1 = *(const u64*)(&Qs[d][tx * 4 + 2]);
        #pragma unroll
        for (int q = 0; q < 4; q++) {
            u64 aq = splat2(a[q]);
            acc[q][0] = ffma2(aq, b0, acc[q][0]);
            acc[q][1] = ffma2(aq, b1, acc[q][1]);
        }
    }

    #pragma unroll
    for (int q = 0; q < 4; q++) {
        float2 o0 = unpack2(acc[q][0]);
        float2 o1 = unpack2(acc[q][1]);
        float4 o = make_float4(o0.x, o0.y, o1.x, o1.y);
        *(float4*)(g_L + (size_t)(i0 + ty * 4 + q) * NN + j0 + tx * 4) = o;
    }
}

// ============================================================
// K3: per-edge MLP, 2 edges per thread packed f32x2.
// v2: layer-2 split into two 16-output halves so live registers stay
// under 255 (no spills); weights pre-splatted in SMEM and fetched as
// LDS.128 (two f32x2 splats per load) -> 512 LDS + 1024 FFMA2 / thread.
// ============================================================
__global__ __launch_bounds__(128) void k_mlp(
    const float* __restrict__ adj, const float* __restrict__ dense,
    const float* __restrict__ W1, const float* __restrict__ b1,
    const float* __restrict__ W2, const float* __restrict__ b2,
    const float* __restrict__ W3, const float* __restrict__ b3)
{
    __shared__ __align__(16) u64 sW1s[FF], sW1a[FF], sW1d[FF], sB1[FF];
    __shared__ __align__(16) u64 sW2[FF * FF];   // splatted, [p][u]
    __shared__ __align__(16) u64 sB2[FF], sW3[FF];
    __shared__ float sB3;

    const int tid = threadIdx.x;
    if (tid < FF) {
        sW1s[tid] = splat2(W1[tid]);
        sW1a[tid] = splat2(W1[FF + tid]);
        sW1d[tid] = splat2(W1[2 * FF + tid]);
        sB1[tid]  = splat2(b1[tid]);
        sB2[tid]  = splat2(b2[tid]);
        sW3[tid]  = splat2(W3[tid]);
    }
    for (int t = tid; t < FF * FF; t += 128) sW2[t] = splat2(W2[t]);
    if (tid == 0) sB3 = b3[0];
    __syncthreads();

    const int i  = blockIdx.y;
    const int jp = blockIdx.x * 128 + tid;
    const size_t off = (size_t)i * NN + (size_t)jp * 2;

    float2 s2 = *(const float2*)(g_L + off);
    float2 a2 = *(const float2*)(adj + off);
    float2 d2 = *(const float2*)(dense + off);
    u64 s = pack2(s2.x, s2.y);
    u64 a = pack2(a2.x, a2.y);
    u64 d = pack2(d2.x, d2.y);

    // layer 1: 3 -> 32  (h1 lives in 64 f32 regs)
    u64 h1[FF];
    #pragma unroll
    for (int u = 0; u < FF; u++) {
        u64 t = ffma2(d, sW1d[u], sB1[u]);
        t = ffma2(a, sW1a[u], t);
        t = ffma2(s, sW1s[u], t);
        h1[u] = relu2(t);
    }

    // layer 2 + layer 3 fused, in two halves of 16 outputs each.
    u64 lg = splat2(sB3);
    #pragma unroll
    for (int half = 0; half < 2; half++) {
        const int u0 = half * 16;
        u64 acc[16];
        #pragma unroll
        for (int u = 0; u < 16; u++) acc[u] = sB2[u0 + u];
        #pragma unroll
        for (int p = 0; p < FF; p++) {
            u64 h = h1[p];
            #pragma unroll
            for (int u = 0; u < 16; u += 2) {
                ulonglong2 w = *(const ulonglong2*)(&sW2[p * FF + u0 + u]);
                acc[u]     = ffma2(h, w.x, acc[u]);
                acc[u + 1] = ffma2(h, w.y, acc[u + 1]);
            }
        }
        #pragma unroll
        for (int u = 0; u < 16; u++)
            lg = ffma2(relu2(acc[u]), sW3[u0 + u], lg);
    }

    *(float2*)(g_L + off) = unpack2(lg);
}

// ============================================================
// K4: per-row softmax prep: in-place e = exp(logit - rowmax),
// g_rs[i] = 1 / rowsum.
// ============================================================
__global__ __launch_bounds__(256) void k_softmax()
{
    __shared__ float red[8];
    const int i = blockIdx.x;
    const int tid = threadIdx.x;
    float4* row = (float4*)(g_L + (size_t)i * NN);

    float4 v0 = row[tid];
    float4 v1 = row[tid + 256];

    float m = fmaxf(fmaxf(fmaxf(v0.x, v0.y), fmaxf(v0.z, v0.w)),
                    fmaxf(fmaxf(v1.x, v1.y), fmaxf(v1.z, v1.w)));
    #pragma unroll
    for (int o = 16; o; o >>= 1) m = fmaxf(m, __shfl_xor_sync(0xffffffffu, m, o));
    if ((tid & 31) == 0) red[tid >> 5] = m;
    __syncthreads();
    float mm = red[0];
    #pragma unroll
    for (int w = 1; w < 8; w++) mm = fmaxf(mm, red[w]);

    v0.x = __expf(v0.x - mm); v0.y = __expf(v0.y - mm);
    v0.z = __expf(v0.z - mm); v0.w = __expf(v0.w - mm);
    v1.x = __expf(v1.x - mm); v1.y = __expf(v1.y - mm);
    v1.z = __expf(v1.z - mm); v1.w = __expf(v1.w - mm);
    row[tid] = v0;
    row[tid + 256] = v1;

    float sum = ((v0.x + v0.y) + (v0.z + v0.w)) + ((v1.x + v1.y) + (v1.z + v1.w));
    #pragma unroll
    for (int o = 16; o; o >>= 1) sum += __shfl_xor_sync(0xffffffffu, sum, o);
    __syncthreads();
    if ((tid & 31) == 0) red[tid >> 5] = sum;
    __syncthreads();
    if (tid == 0) {
        float tot = 0.0f;
        #pragma unroll
        for (int w = 0; w < 8; w++) tot += red[w];
        g_rs[i] = 1.0f / tot;
    }
}

// ============================================================
// K5: out[i][c] = (1/rowsum_i) * sum_j E[i][j] * v[j][c]
// ============================================================
__global__ __launch_bounds__(256) void k_av(float* __restrict__ out)
{
    __shared__ __align__(16) float Es[32][68];
    __shared__ __align__(16) float Vs[32][64];

    const int tid = threadIdx.x;
    const int tx = tid & 15;
    const int ty = tid >> 4;
    const int r0 = blockIdx.y * 64;
    const int c0 = blockIdx.x * 64;

    u64 acc[4][2] = {};

    for (int k0 = 0; k0 < NN; k0 += 32) {
        __syncthreads();
        #pragma unroll
        for (int it = 0; it < 2; it++) {
            int idx = tid + it * 256;
            int rr = idx >> 3;
            int cc = idx & 7;
            float4 ev = *(const float4*)(g_L + (size_t)(r0 + rr) * NN + k0 + cc * 4);
            Es[cc * 4 + 0][rr] = ev.x; Es[cc * 4 + 1][rr] = ev.y;
            Es[cc * 4 + 2][rr] = ev.z; Es[cc * 4 + 3][rr] = ev.w;
        }
        #pragma unroll
        for (int it = 0; it < 2; it++) {
            int idx = tid + it * 256;
            int rr = idx >> 4;
            int cc = idx & 15;
            *(float4*)(&Vs[rr][cc * 4]) =
                *(const float4*)(g_v + (size_t)(k0 + rr) * DHH + c0 + cc * 4);
        }
        __syncthreads();
        #pragma unroll
        for (int kk = 0; kk < 32; kk++) {
            float a[4];
            *(float4*)a = *(const float4*)(&Es[kk][ty * 4]);
            u64 b0 = *(const u64*)(&Vs[kk][tx * 4]);
            u64 b1 = *(const u64*)(&Vs[kk][tx * 4 + 2]);
            #pragma unroll
            for (int q = 0; q < 4; q++) {
                u64 aq = splat2(a[q]);
                acc[q][0] = ffma2(aq, b0, acc[q][0]);
                acc[q][1] = ffma2(aq, b1, acc[q][1]);
            }
        }
    }

    #pragma unroll
    for (int q = 0; q < 4; q++) {
        int r = r0 + ty * 4 + q;
        float rs = g_rs[r];
        float2 o0 = unpack2(acc[q][0]);
        float2 o1 = unpack2(acc[q][1]);
        float4 o = make_float4(o0.x * rs, o0.y * rs, o1.x * rs, o1.y * rs);
        *(float4*)(out + (size_t)r * DHH + c0 + tx * 4) = o;
    }
}

// ============================================================
extern "C" void kernel_launch(void* const* d_in, const int* in_sizes, int n_in,
                              void* d_out, int out_size)
{
    (void)in_sizes; (void)n_in; (void)out_size;
    const float* x     = (const float*)d_in[0];
    const float* adj   = (const float*)d_in[1];
    const float* dense = (const float*)d_in[2];
    const float* Wq    = (const float*)d_in[3];
    const float* bq    = (const float*)d_in[4];
    const float* Wk    = (const float*)d_in[5];
    const float* bk    = (const float*)d_in[6];
    const float* Wv    = (const float*)d_in[7];
    const float* bv    = (const float*)d_in[8];
    const float* W1    = (const float*)d_in[9];
    const float* b1    = (const float*)d_in[10];
    const float* W2    = (const float*)d_in[11];
    const float* b2    = (const float*)d_in[12];
    const float* W3    = (const float*)d_in[13];
    const float* b3    = (const float*)d_in[14];
    float* out = (float*)d_out;

    float *qp, *kp, *vp;
    cudaGetSymbolAddress((void**)&qp, g_q);
    cudaGetSymbolAddress((void**)&kp, g_k);
    cudaGetSymbolAddress((void**)&vp, g_v);

    // K1: projections (q and k fused into one launch via blockIdx.z)
    k_gemm_qk<<<dim3(1, NN / 64, 2), 256>>>(x, Wq, bq, Wk, bk, qp, kp);
    k_gemm_v<<<dim3(DHH / 64, NN / 64), 256>>>(x, Wv, bv, vp);
    // K2: scores = k @ q^T -> g_L
    k_scores<<<dim3(NN / 64, NN / 64), 256>>>();
    // K3: per-edge MLP -> logits in place
    k_mlp<<<dim3(NN / 256, NN), 128>>>(adj, dense, W1, b1, W2, b2, W3, b3);
    // K4: exp(logit - rowmax) in place + 1/rowsum
    k_softmax<<<NN, 256>>>();
    // K5: feature = focus @ v
    k_av<<<dim3(DHH / 64, NN / 64), 256>>>(out);
}